// round 14
// baseline (speedup 1.0000x reference)
#include <cuda_runtime.h>
#include <cstdint>

// Problem constants
#define NB   32
#define NS   128
#define NW   4096      // NB*NS independent words
#define CC   32        // chars per word (time steps)
#define HH   256       // hidden
#define G3   768       // 3*H
#define EE   128       // embed dim
#define NV   262       // vocab
#define WPB  16        // words per block
#define HROW 20        // padded smem row for h (16 words + pad, 16B aligned)
#define NTILES (NW / WPB)           // 256

typedef unsigned long long u64;

// Precomputed x-projection table: P[d][v][j] = embed[v].W_ih[d][j] + b_ih[d][j]
// (+ b_hh[j] folded in for the r and z gates, j < 512)
__device__ float g_P[2][NV][G3];
// k-major transposed input weights (for coalesced prep_p)
__device__ float g_WtI[2][EE][G3];
// k-quad packed recurrent weights: g_W4[d][k4][g][j] = W_hh[g*256+j][4k4..4k4+3]
// one PAD slot at k4 = HH/4 so the gru prefetch needs no end-clamp
__device__ float4 g_W4[2][HH / 4 + 1][3][256];
// length-sort structures
__device__ int g_len[NW];          // per-word char length
__device__ int g_perm[NW];         // word ids sorted by length DESCENDING
__device__ int g_bucket_pos[33];   // scatter cursors

// ---------------------------------------------------------------------------
// Packed fp32x2 helpers (Blackwell 2x-rate fp32; ptxas never auto-emits)
// ---------------------------------------------------------------------------
__device__ __forceinline__ void fma2(u64& d, u64 a, u64 b) {
    asm("fma.rn.f32x2 %0, %1, %2, %3;" : "=l"(d) : "l"(a), "l"(b), "l"(d));
}
__device__ __forceinline__ u64 dup2(float x) {
    u64 r;
    asm("mov.b64 %0, {%1, %1};" : "=l"(r) : "f"(x));
    return r;
}
// single-MUFU reciprocal (rcp.approx, same core op __fdividef uses)
__device__ __forceinline__ float frcp(float x) {
    float r;
    asm("rcp.approx.f32 %0, %1;" : "=f"(r) : "f"(x));
    return r;
}
__device__ __forceinline__ float clampf(float x, float lo, float hi) {
    return fmaxf(lo, fminf(hi, x));
}

// ---------------------------------------------------------------------------
// Prepack 0: transpose W_ih (768x128) to k-major (for coalesced prep_p).
// ---------------------------------------------------------------------------
__global__ void prep_tr_kernel(const float* __restrict__ Wih_fw,
                               const float* __restrict__ Wih_bw)
{
    int j = blockIdx.x;
    int d = blockIdx.y;
    int k = threadIdx.x;
    const float* Wi = d ? Wih_bw : Wih_fw;
    g_WtI[d][k][j] = Wi[(size_t)j * EE + k];
}

// ---------------------------------------------------------------------------
// Prepack 1: k-quad packed weight table straight from W_hh (row-major).
// ---------------------------------------------------------------------------
__global__ void prep_w4_kernel(const float* __restrict__ Whh_fw,
                               const float* __restrict__ Whh_bw)
{
    const int row = blockIdx.x;          // j-row of W_hh: gate g = row/256
    const int d   = blockIdx.y;
    const int k4  = threadIdx.x;         // 0..63
    const float* W = d ? Whh_bw : Whh_fw;
    float4 v = reinterpret_cast<const float4*>(W + (size_t)row * HH)[k4];
    g_W4[d][k4][row >> 8][row & 255] = v;
    if (k4 == 0)                          // zero the pad slot once per row
        g_W4[d][HH / 4][row >> 8][row & 255] = make_float4(0.f, 0.f, 0.f, 0.f);
}

// ---------------------------------------------------------------------------
// Prepack 2: input-projection table, coalesced via g_WtI.  grid (NV, 2).
// ---------------------------------------------------------------------------
__global__ void prep_p_kernel(const float* __restrict__ embed,
                              const float* __restrict__ bih_fw,
                              const float* __restrict__ bhh_fw,
                              const float* __restrict__ bih_bw,
                              const float* __restrict__ bhh_bw)
{
    int v = blockIdx.x;
    int d = blockIdx.y;
    int tid = threadIdx.x;
    const float* bi = d ? bih_bw : bih_fw;
    const float* bh = d ? bhh_bw : bhh_fw;
    const float* ev = embed + (size_t)v * EE;
    float a0 = 0.f, a1 = 0.f, a2 = 0.f;
#pragma unroll 4
    for (int k = 0; k < EE; k++) {
        float e = __ldg(ev + k);                        // warp-broadcast
        const float* w = &g_WtI[d][k][0];
        a0 = fmaf(e, __ldg(w + tid),       a0);
        a1 = fmaf(e, __ldg(w + tid + 256), a1);
        a2 = fmaf(e, __ldg(w + tid + 512), a2);
    }
    g_P[d][v][tid]       = a0 + bi[tid]       + bh[tid];
    g_P[d][v][tid + 256] = a1 + bi[tid + 256] + bh[tid + 256];
    g_P[d][v][tid + 512] = a2 + bi[tid + 512];          // n-gate: b_hh NOT folded
}

// ---------------------------------------------------------------------------
// Prepack 3a: per-word lengths, grid-parallel (contiguous-prefix mask).
// ---------------------------------------------------------------------------
__global__ void prep_len_kernel(const int* __restrict__ chars_mask)
{
    const int n = blockIdx.x * blockDim.x + threadIdx.x;
    const int4* row = reinterpret_cast<const int4*>(chars_mask + n * CC);
    int len = 0;
#pragma unroll
    for (int c = 0; c < CC / 4; c++) {
        int4 m = __ldg(row + c);
        len += m.x + m.y + m.z + m.w;
    }
    g_len[n] = len;
}

// ---------------------------------------------------------------------------
// Prepack 3b: counting sort by length DESCENDING (reads only g_len).
// ---------------------------------------------------------------------------
__global__ void prep_sort_kernel()
{
    __shared__ int hist[33];
    __shared__ int base[33];
    const int tid = threadIdx.x;
    if (tid < 33) hist[tid] = 0;
    __syncthreads();

    int mylen[NW / 1024];
#pragma unroll
    for (int q = 0; q < NW / 1024; q++) {
        mylen[q] = g_len[tid + q * 1024];
        atomicAdd(&hist[32 - mylen[q]], 1);
    }
    __syncthreads();

    if (tid == 0) {
        int acc = 0;
        for (int b = 0; b < 33; b++) { base[b] = acc; acc += hist[b]; }
    }
    __syncthreads();
    if (tid < 33) g_bucket_pos[tid] = base[tid];
    __syncthreads();

#pragma unroll
    for (int q = 0; q < NW / 1024; q++) {
        const int pos = atomicAdd(&g_bucket_pos[32 - mylen[q]], 1);
        g_perm[pos] = tid + q * 1024;
    }
}

// rank-1 update for one k: acc[word-pairs] += h[word-pairs] * w_gate
__device__ __forceinline__ void k_rank1(const float* __restrict__ hrow,
                                        float wr, float wz, float wn,
                                        u64* accr, u64* accz, u64* accn)
{
    const u64 wr2 = dup2(wr);
    const u64 wz2 = dup2(wz);
    const u64 wn2 = dup2(wn);
    const ulonglong2* __restrict__ hk = reinterpret_cast<const ulonglong2*>(hrow);
#pragma unroll
    for (int q = 0; q < WPB / 4; q++) {                  // 4 LDS.128 broadcast
        ulonglong2 a = hk[q];                            // words 4q..4q+3
        fma2(accr[2 * q],     a.x, wr2);
        fma2(accz[2 * q],     a.x, wz2);
        fma2(accn[2 * q],     a.x, wn2);
        fma2(accr[2 * q + 1], a.y, wr2);
        fma2(accz[2 * q + 1], a.y, wz2);
        fma2(accn[2 * q + 1], a.y, wn2);
    }
}

// ---------------------------------------------------------------------------
// Main recurrent kernel (R12 + MUFU-reduced epilogue).
// GEMV identical to R12.  Epilogue: per word-pair, the 4 sigmoid divisions
// share ONE rcp (combined denominators) and the 2 tanh divisions share ONE
// rcp -> 8 MUFU per 2 words instead of 12.  Exact math (re-associated
// division only); inputs clamped +-20 so products stay finite.  Whole
// 4-word groups past their length are skipped (lengths descend in-tile).
// ---------------------------------------------------------------------------
__global__ void __launch_bounds__(256, 2) gru_kernel(
    const int*   __restrict__ chars,       // [NW, CC]
    const int*   __restrict__ data_mask,   // [NW]
    const float* __restrict__ bhh_fw,      // [G3]
    const float* __restrict__ bhh_bw,
    float*       __restrict__ out)         // [NW, 512]
{
    __shared__ float hsm[2][HH * HROW];    // double-buffered h, 40KB
    __shared__ int   wid_s[WPB];           // real word ids of this tile
    __shared__ int   len_s[WPB];           // per-word lengths
    __shared__ int   chs[WPB][CC];         // per-tile char ids, 2KB

    const int tid  = threadIdx.x;
    const int tile = blockIdx.x >> 1;
    const int d    = blockIdx.x & 1;

    const float4* __restrict__ W4 =
        reinterpret_cast<const float4*>(&g_W4[d][0][0][0]);  // [(k4*3+g)*256+j]
    const float bn = (d ? bhh_bw : bhh_fw)[tid + 512];       // n-gate bias

    if (tid < WPB) {
        const int n = g_perm[tile * WPB + tid];
        wid_s[tid] = n;
        len_s[tid] = g_len[n];
    }
    const int maxlen = __ldg(&g_len[__ldg(&g_perm[tile * WPB])]);  // first = longest

    // init h buffer 0 = 0
#pragma unroll
    for (int q = 0; q < HH * HROW / 256; q++)           // 20 stores/thread
        hsm[0][tid + q * 256] = 0.f;
    __syncthreads();

    // preload this tile's chars into smem (2 per thread)
#pragma unroll
    for (int q = 0; q < WPB * CC / 256; q++) {
        const int idx = tid + q * 256;
        const int w   = idx / CC;
        const int c   = idx % CC;
        chs[w][c] = __ldg(&chars[wid_s[w] * CC + c]);
    }
    __syncthreads();

    for (int step = 0; step < maxlen; step++) {
        const int t = d ? (maxlen - 1 - step) : step;
        const float* __restrict__ rb = hsm[step & 1];        // read buffer
        float*       __restrict__ wbv = hsm[(step + 1) & 1]; // write buffer

        // accumulators: 8 word-pairs x 3 gates, packed fp32x2
        u64 accr[WPB / 2], accz[WPB / 2], accn[WPB / 2];
#pragma unroll
        for (int p = 0; p < WPB / 2; p++) { accr[p] = 0ull; accz[p] = 0ull; accn[p] = 0ull; }

        // ---- gh = h @ W_hh^T; 4 k per iter, padded prefetch (no clamp) -----
        float4 c0 = __ldg(W4 + 0 * 256 + tid);           // r-gate, k 0..3
        float4 c1 = __ldg(W4 + 1 * 256 + tid);           // z-gate
        float4 c2 = __ldg(W4 + 2 * 256 + tid);           // n-gate
#pragma unroll 4
        for (int kg = 0; kg < HH / 4; kg++) {
            const int kn = kg + 1;                       // pad slot makes this safe
            float4 p0 = __ldg(W4 + (kn * 3 + 0) * 256 + tid);
            float4 p1 = __ldg(W4 + (kn * 3 + 1) * 256 + tid);
            float4 p2 = __ldg(W4 + (kn * 3 + 2) * 256 + tid);

            k_rank1(&rb[(4 * kg + 0) * HROW], c0.x, c1.x, c2.x, accr, accz, accn);
            k_rank1(&rb[(4 * kg + 1) * HROW], c0.y, c1.y, c2.y, accr, accz, accn);
            k_rank1(&rb[(4 * kg + 2) * HROW], c0.z, c1.z, c2.z, accr, accz, accn);
            k_rank1(&rb[(4 * kg + 3) * HROW], c0.w, c1.w, c2.w, accr, accz, accn);

            c0 = p0; c1 = p1; c2 = p2;
        }

        // ---- gates, MUFU-batched, into the OTHER buffer --------------------
        const float* ar = reinterpret_cast<const float*>(accr);
        const float* az = reinterpret_cast<const float*>(accz);
        const float* an = reinterpret_cast<const float*>(accn);
#pragma unroll
        for (int g4 = 0; g4 < WPB / 4; g4++) {
            const int w0 = 4 * g4;
            if (t >= len_s[w0]) {                        // whole group frozen
#pragma unroll
                for (int j = 0; j < 4; j++)
                    wbv[tid * HROW + w0 + j] = rb[tid * HROW + w0 + j];
                continue;
            }
            float xr[4], xz[4], xn[4], hold[4];
#pragma unroll
            for (int j = 0; j < 4; j++) {                // batch loads (MLP)
                const int w = w0 + j;
                const float* __restrict__ Prow = &g_P[d][chs[w][t]][0];
                xr[j] = __ldg(Prow + tid);               // b_ih + b_hh folded
                xz[j] = __ldg(Prow + tid + 256);
                xn[j] = __ldg(Prow + tid + 512);         // b_ih only
                hold[j] = rb[tid * HROW + w];
            }
#pragma unroll
            for (int p = 0; p < 2; p++) {                // word pairs
                const int j0 = 2 * p, j1 = 2 * p + 1;
                const int wA = w0 + j0, wB = w0 + j1;
                // sigmoid inputs, clamped so 4-term products stay finite
                float a0 = clampf(xr[j0] + ar[wA], -20.f, 20.f);
                float b0 = clampf(xz[j0] + az[wA], -20.f, 20.f);
                float a1 = clampf(xr[j1] + ar[wB], -20.f, 20.f);
                float b1 = clampf(xz[j1] + az[wB], -20.f, 20.f);
                float u0 = __expf(-a0), v0 = __expf(-b0);
                float u1 = __expf(-a1), v1 = __expf(-b1);
                float A0 = 1.f + u0, B0 = 1.f + v0;
                float A1 = 1.f + u1, B1 = 1.f + v1;
                float P0 = A0 * B0, P1 = A1 * B1;
                float R  = frcp(P0 * P1);                // ONE rcp for 4 sigmoids
                float s1 = P1 * R, s0 = P0 * R;
                float r0 = B0 * s1, z0 = A0 * s1;        // = 1/A0, 1/B0
                float r1 = B1 * s0, z1 = A1 * s0;
                // tanh pair, one shared rcp
                float hn0 = bn + an[wA], hn1 = bn + an[wB];
                float cc0 = clampf(fmaf(r0, hn0, xn[j0]), -15.f, 15.f);
                float cc1 = clampf(fmaf(r1, hn1, xn[j1]), -15.f, 15.f);
                float w0e = __expf(-2.f * cc0), w1e = __expf(-2.f * cc1);
                float E0 = 1.f + w0e, E1 = 1.f + w1e;
                float RE = frcp(E0 * E1);                // ONE rcp for 2 tanh
                float n0 = (1.f - w0e) * E1 * RE;
                float n1 = (1.f - w1e) * E0 * RE;
                float h0 = (1.f - z0) * n0 + z0 * hold[j0];
                float h1 = (1.f - z1) * n1 + z1 * hold[j1];
                wbv[tid * HROW + wA] = (t < len_s[wA]) ? h0 : hold[j0];
                wbv[tid * HROW + wB] = (t < len_s[wB]) ? h1 : hold[j1];
            }
        }
        __syncthreads();                                 // wbv visible; rb free
    }

    // ---- final write: out[n, d*256 + i] = h * data_mask[n] -----------------
    const float* hb = hsm[maxlen & 1];
#pragma unroll
    for (int w = 0; w < WPB; w++) {
        const int n = wid_s[w];
        const float dm = data_mask[n] ? 1.f : 0.f;
        out[(size_t)n * 512 + d * 256 + tid] = hb[tid * HROW + w] * dm;
    }
}

// ---------------------------------------------------------------------------
extern "C" void kernel_launch(void* const* d_in, const int* in_sizes, int n_in,
                              void* d_out, int out_size)
{
    const int*   chars      = (const int*)  d_in[0];
    const int*   chars_mask = (const int*)  d_in[1];
    const int*   data_mask  = (const int*)  d_in[2];
    const float* embed      = (const float*)d_in[3];
    const float* Wih_fw     = (const float*)d_in[4];
    const float* Whh_fw     = (const float*)d_in[5];
    const float* bih_fw     = (const float*)d_in[6];
    const float* bhh_fw     = (const float*)d_in[7];
    const float* Wih_bw     = (const float*)d_in[8];
    const float* Whh_bw     = (const float*)d_in[9];
    const float* bih_bw     = (const float*)d_in[10];
    const float* bhh_bw     = (const float*)d_in[11];
    float* out = (float*)d_out;

    prep_tr_kernel<<<dim3(G3, 2), EE>>>(Wih_fw, Wih_bw);
    prep_w4_kernel<<<dim3(G3, 2), HH / 4>>>(Whh_fw, Whh_bw);
    prep_p_kernel<<<dim3(NV, 2), 256>>>(embed, bih_fw, bhh_fw, bih_bw, bhh_bw);
    prep_len_kernel<<<NW / 256, 256>>>(chars_mask);
    prep_sort_kernel<<<1, 1024>>>();
    gru_kernel<<<dim3(2 * NTILES, 1), 256>>>(chars, data_mask, bhh_fw, bhh_bw, out);
}